// round 2
// baseline (speedup 1.0000x reference)
#include <cuda_runtime.h>

#define HID 64
#define MAXN 500000

typedef unsigned long long ull;

__device__ __forceinline__ ull pack2(float lo, float hi) {
    ull r; asm("mov.b64 %0, {%1,%2};" : "=l"(r) : "f"(lo), "f"(hi)); return r;
}
__device__ __forceinline__ void unpack2(ull v, float& lo, float& hi) {
    asm("mov.b64 {%0,%1}, %2;" : "=f"(lo), "=f"(hi) : "l"(v));
}
__device__ __forceinline__ void fma2(ull& d, ull a, ull b) {
    asm("fma.rn.f32x2 %0, %1, %2, %0;" : "+l"(d) : "l"(a), "l"(b));
}

// ---------------- scratch (device globals; allocation-free rule) ----------------
__device__ float g_h[50000 * HID];        // node features
__device__ float g_e[500000 * HID];       // graph-edge features
__device__ float g_l[800000 * HID];       // line-graph-edge features
__device__ float g_A[MAXN * HID];         // Ah
__device__ float g_B[MAXN * HID];         // Bh
__device__ float g_D[MAXN * HID];         // Dh
__device__ float g_E[MAXN * HID];         // Eh
__device__ float g_accsh[MAXN * HID];     // segment_sum(Bh[src]*sigma)
__device__ float g_accs[MAXN * HID];      // segment_sum(sigma)
__device__ int   g_off[2048];             // crystal offsets

// ---------------- kernels ----------------

__global__ void embed_kernel(const int* __restrict__ an,
                             const float* __restrict__ emb, int n) {
    int i = blockIdx.x * blockDim.x + threadIdx.x;
    if (i < n * HID) g_h[i] = emb[an[i >> 6] * HID + (i & 63)];
}

// out[row] = rbf(x[row]) @ W + b ; bins <= 80
__global__ void rbf_kernel(const float* __restrict__ x, const float* __restrict__ W,
                           const float* __restrict__ bias, float* __restrict__ out,
                           int n, int bins, float vmin, float step, float gamma) {
    __shared__ float phi[8 * 80];
    __shared__ float xs[8];
    int tx = threadIdx.x & 31, ez = threadIdx.x >> 5;
    ull bp = *(const ull*)(bias + 2 * tx);
    for (int base = blockIdx.x * 8; base < n; base += gridDim.x * 8) {
        __syncthreads();
        if (threadIdx.x < 8)
            xs[threadIdx.x] = (base + threadIdx.x < n) ? x[base + threadIdx.x] : 0.f;
        __syncthreads();
        for (int idx = threadIdx.x; idx < 8 * bins; idx += 256) {
            int ee = idx / bins, k = idx - ee * bins;
            float dd = xs[ee] - (vmin + k * step);
            phi[idx] = __expf(-gamma * dd * dd);
        }
        __syncthreads();
        int eid = base + ez;
        if (eid < n) {
            ull acc = bp;
            for (int k = 0; k < bins; k++) {
                float p = phi[ez * bins + k];
                fma2(acc, pack2(p, p), __ldg((const ull*)(W + k * HID + 2 * tx)));
            }
            *(ull*)(out + (size_t)eid * HID + 2 * tx) = acc;
        }
    }
}

// A/B/D/E projections for all n rows of h; also zeroes accumulators.
// W points at layer base [5][64][64]; bias at [5][64].
__global__ void proj4_kernel(const float* __restrict__ h, const float* __restrict__ W,
                             const float* __restrict__ bias, int n) {
    __shared__ __align__(16) float hs[32 * HID];
    int tx = threadIdx.x & 31, wy = threadIdx.x >> 5;
    const float* W0 = W;
    const float* W1 = W + 4096;
    const float* W3 = W + 3 * 4096;
    const float* W4 = W + 4 * 4096;
    ull b0 = *(const ull*)(bias + 0 * 64 + 2 * tx);
    ull b1 = *(const ull*)(bias + 1 * 64 + 2 * tx);
    ull b3 = *(const ull*)(bias + 3 * 64 + 2 * tx);
    ull b4 = *(const ull*)(bias + 4 * 64 + 2 * tx);
    for (int base = blockIdx.x * 32; base < n; base += gridDim.x * 32) {
        int nrows = min(32, n - base);
        __syncthreads();
        for (int i = threadIdx.x; i < nrows * HID; i += 256)
            hs[i] = h[(size_t)base * HID + i];
        __syncthreads();
        ull a0[4], a1[4], a3[4], a4[4];
#pragma unroll
        for (int r = 0; r < 4; r++) { a0[r] = b0; a1[r] = b1; a3[r] = b3; a4[r] = b4; }
        int r0 = wy * 4;
#pragma unroll 4
        for (int k = 0; k < HID; k++) {
            ull w0 = __ldg((const ull*)(W0 + k * 64 + 2 * tx));
            ull w1 = __ldg((const ull*)(W1 + k * 64 + 2 * tx));
            ull w3 = __ldg((const ull*)(W3 + k * 64 + 2 * tx));
            ull w4 = __ldg((const ull*)(W4 + k * 64 + 2 * tx));
#pragma unroll
            for (int r = 0; r < 4; r++) {
                float hv = hs[(r0 + r) * HID + k];
                ull h2 = pack2(hv, hv);
                fma2(a0[r], h2, w0);
                fma2(a1[r], h2, w1);
                fma2(a3[r], h2, w3);
                fma2(a4[r], h2, w4);
            }
        }
#pragma unroll
        for (int r = 0; r < 4; r++) {
            int row = base + r0 + r;
            if (row < n) {
                size_t o = (size_t)row * HID + 2 * tx;
                *(ull*)(g_A + o) = a0[r];
                *(ull*)(g_B + o) = a1[r];
                *(ull*)(g_D + o) = a3[r];
                *(ull*)(g_E + o) = a4[r];
                *(ull*)(g_accsh + o) = 0ull;
                *(ull*)(g_accs + o)  = 0ull;
            }
        }
    }
}

// Per-edge: Ce = e@W2+b2 (W2 in smem), e_new = Dh[src]+Eh[dst]+Ce,
// sigma=sigmoid, atomic segment sums into g_accsh/g_accs, optional in-place e update.
// Each warp handles 2 edges (shares the W2 shared reads).
__global__ void edge_kernel(const int* __restrict__ src, const int* __restrict__ dst,
                            const float* __restrict__ W2, const float* __restrict__ b2,
                            float* __restrict__ e, int E, int write_e) {
    __shared__ __align__(16) float W2s[64 * 64];
    __shared__ ull esd[16 * 64];
    __shared__ int ssrc[16], sdst[16];
    for (int i = threadIdx.x; i < 4096; i += 256) W2s[i] = W2[i];
    int tx = threadIdx.x & 31, wz = threadIdx.x >> 5;  // warp 0..7
    ull b2p = *(const ull*)(b2 + 2 * tx);
    for (int base = blockIdx.x * 16; base < E; base += gridDim.x * 16) {
        __syncthreads();
        if (threadIdx.x < 16 && base + threadIdx.x < E) {
            ssrc[threadIdx.x] = src[base + threadIdx.x];
            sdst[threadIdx.x] = dst[base + threadIdx.x];
        }
        for (int idx = threadIdx.x; idx < 16 * 64; idx += 256) {
            int ee = idx >> 6, k = idx & 63;
            float v = 0.f;
            if (base + ee < E) v = e[(size_t)(base + ee) * HID + k];
            esd[idx] = pack2(v, v);
        }
        __syncthreads();
        int ea = base + 2 * wz;
        int eb = ea + 1;
        bool va = ea < E, vb = eb < E;
        ull ceA = b2p, ceB = b2p;
        // straight-line, fully unrolled dual matvec (zero-padded rows for
        // out-of-range edges, so no predication in the hot loop)
#pragma unroll
        for (int k = 0; k < 64; k++) {
            ull w = *(const ull*)&W2s[k * 64 + 2 * tx];
            fma2(ceA, esd[(2 * wz) * 64 + k], w);
            fma2(ceB, esd[(2 * wz + 1) * 64 + k], w);
        }
#pragma unroll
        for (int half = 0; half < 2; half++) {
            int eid = (half == 0) ? ea : eb;
            bool valid = (half == 0) ? va : vb;
            if (!valid) continue;
            int lz = 2 * wz + half;
            int s = ssrc[lz], d = sdst[lz];
            float c0, c1; unpack2((half == 0) ? ceA : ceB, c0, c1);
            size_t so = (size_t)s * HID + 2 * tx;
            size_t dofs = (size_t)d * HID + 2 * tx;
            float2 dh = __ldg((const float2*)(g_D + so));
            float2 eh = __ldg((const float2*)(g_E + dofs));
            float2 bh = __ldg((const float2*)(g_B + so));
            float en0 = dh.x + eh.x + c0;
            float en1 = dh.y + eh.y + c1;
            float sg0 = 1.f / (1.f + __expf(-en0));
            float sg1 = 1.f / (1.f + __expf(-en1));
            atomicAdd(g_accsh + dofs,     bh.x * sg0);
            atomicAdd(g_accsh + dofs + 1, bh.y * sg1);
            atomicAdd(g_accs + dofs,      sg0);
            atomicAdd(g_accs + dofs + 1,  sg1);
            if (write_e) {
                float e0, e1, junk;
                unpack2(esd[lz * 64 + 2 * tx], e0, junk);
                unpack2(esd[lz * 64 + 2 * tx + 1], e1, junk);
                float2 eo;
                eo.x = e0 + en0 * sg0;   // silu(en) = en * sigmoid(en)
                eo.y = e1 + en1 * sg1;
                *(float2*)(e + (size_t)eid * HID + 2 * tx) = eo;
            }
        }
    }
}

__global__ void node_kernel(float* __restrict__ h, int n) {
    int i = blockIdx.x * blockDim.x + threadIdx.x;
    if (i < n * HID) {
        float hn = g_A[i] + g_accsh[i] / (g_accs[i] + 1e-6f);
        h[i] += hn / (1.f + __expf(-hn));
    }
}

__global__ void offsets_kernel(const int* __restrict__ len, int Bc) {
    if (threadIdx.x == 0 && blockIdx.x == 0) {
        int o = 0;
        for (int b = 0; b < Bc && b < 2048; b++) { g_off[b] = o; o += len[b]; }
    }
}

// Fused FC + reconstruct_batch. One block per (b, j) row.
__global__ void out_kernel(const float* __restrict__ h, const float* __restrict__ fcW,
                           const float* __restrict__ fcb, const int* __restrict__ len,
                           float* __restrict__ out, int n_nodes, int Bc, int L, int TH,
                           int with_mask) {
    __shared__ float hsh[HID];
    int row = blockIdx.x;
    int b = row / L, j = row - b * L;
    int lenb = len[b];
    int m = (j < lenb) ? 1 : 0;
    if (with_mask && threadIdx.x == 0)
        out[(size_t)Bc * L * TH + row] = (float)m;
    size_t ro = (size_t)row * TH;
    if (!m) {
        for (int t = threadIdx.x; t < TH; t += blockDim.x) out[ro + t] = 0.f;
        return;
    }
    int node = g_off[b] + j;
    if (node >= n_nodes) node = n_nodes - 1;
    if (node < 0) node = 0;
    if (threadIdx.x < HID) hsh[threadIdx.x] = h[(size_t)node * HID + threadIdx.x];
    __syncthreads();
    for (int t = threadIdx.x; t < TH; t += blockDim.x) {
        float acc = fcb[t];
#pragma unroll
        for (int k = 0; k < HID; k++)
            acc = fmaf(hsh[k], __ldg(fcW + k * TH + t), acc);
        out[ro + t] = acc;
    }
}

// ---------------- host ----------------

extern "C" void kernel_launch(void* const* d_in, const int* in_sizes, int n_in,
                              void* d_out, int out_size) {
    const int*   an   = (const int*)d_in[0];
    const int*   src  = (const int*)d_in[1];
    const int*   dst  = (const int*)d_in[2];
    const int*   lsrc = (const int*)d_in[3];
    const int*   ldst = (const int*)d_in[4];
    const float* dist = (const float*)d_in[5];
    const float* ang  = (const float*)d_in[6];
    const int*   clen = (const int*)d_in[7];
    const float* emb  = (const float*)d_in[8];
    const float* eW   = (const float*)d_in[9];
    const float* eb   = (const float*)d_in[10];
    const float* aW   = (const float*)d_in[11];
    const float* ab   = (const float*)d_in[12];
    const float* Wg   = (const float*)d_in[13];
    const float* bg   = (const float*)d_in[14];
    const float* fcW  = (const float*)d_in[15];
    const float* fcb  = (const float*)d_in[16];

    int n_nodes = in_sizes[0];
    int n_edges = in_sizes[1];
    int n_lg    = in_sizes[3];
    int Bc      = in_sizes[7];
    int rbf_d   = in_sizes[9] / HID;    // 80
    int rbf_t   = in_sizes[11] / HID;   // 40
    int TH      = in_sizes[15] / HID;   // 256

    float *p_h, *p_e, *p_l;
    cudaGetSymbolAddress((void**)&p_h, g_h);
    cudaGetSymbolAddress((void**)&p_e, g_e);
    cudaGetSymbolAddress((void**)&p_l, g_l);

    long long per = (long long)out_size / Bc;
    int L, with_mask;
    if (per % (TH + 1) == 0) { L = (int)(per / (TH + 1)); with_mask = 1; }
    else                     { L = (int)(per / TH);       with_mask = 0; }

    const int GS = 148 * 8;

    embed_kernel<<<(n_nodes * HID + 255) / 256, 256>>>(an, emb, n_nodes);
    rbf_kernel<<<GS, 256>>>(dist, eW, eb, p_e, n_edges, rbf_d,
                            0.f, 8.f / (rbf_d - 1), (rbf_d - 1) / 8.f);
    rbf_kernel<<<GS, 256>>>(ang, aW, ab, p_l, n_lg, rbf_t,
                            -1.f, 2.f / (rbf_t - 1), (rbf_t - 1) / 2.f);

    struct GcnArgs { const int* s; const int* d; int n; int E; float* hb; float* ebuf; int layer; int we; };
    GcnArgs seq[6] = {
        { src,  dst,  n_nodes, n_edges, p_h, p_e, 0, 1 },
        { lsrc, ldst, n_edges, n_lg,    p_e, p_l, 1, 1 },
        { src,  dst,  n_nodes, n_edges, p_h, p_e, 2, 1 },
        { lsrc, ldst, n_edges, n_lg,    p_e, p_l, 3, 1 },
        { src,  dst,  n_nodes, n_edges, p_h, p_e, 4, 0 },  // trailing: e_out discarded
        { src,  dst,  n_nodes, n_edges, p_h, p_e, 5, 0 },
    };
    for (int i = 0; i < 6; i++) {
        const GcnArgs& a = seq[i];
        const float* Wl = Wg + (size_t)a.layer * 5 * 4096;
        const float* bl = bg + (size_t)a.layer * 5 * 64;
        proj4_kernel<<<GS, 256>>>(a.hb, Wl, bl, a.n);
        edge_kernel<<<GS, 256>>>(a.s, a.d, Wl + 2 * 4096, bl + 2 * 64, a.ebuf, a.E, a.we);
        node_kernel<<<(a.n * HID + 255) / 256, 256>>>(a.hb, a.n);
    }

    offsets_kernel<<<1, 32>>>(clen, Bc);
    out_kernel<<<Bc * L, 256>>>(p_h, fcW, fcb, clen, (float*)d_out,
                                n_nodes, Bc, L, TH, with_mask);
}

// round 3
// speedup vs baseline: 1.1796x; 1.1796x over previous
#include <cuda_runtime.h>

#define HID 64
#define MAXN 500000
#define MAXE 800000

typedef unsigned long long ull;

__device__ __forceinline__ ull pack2(float lo, float hi) {
    ull r; asm("mov.b64 %0, {%1,%2};" : "=l"(r) : "f"(lo), "f"(hi)); return r;
}
__device__ __forceinline__ void unpack2(ull v, float& lo, float& hi) {
    asm("mov.b64 {%0,%1}, %2;" : "=f"(lo), "=f"(hi) : "l"(v));
}
__device__ __forceinline__ void fma2(ull& d, ull a, ull b) {
    asm("fma.rn.f32x2 %0, %1, %2, %0;" : "+l"(d) : "l"(a), "l"(b));
}

// ---------------- scratch (device globals; allocation-free rule) ----------------
__device__ float g_h[50000 * HID];
__device__ float g_e[500000 * HID];
__device__ float g_l[800000 * HID];
__device__ float g_A[MAXN * HID];
__device__ float g_B[MAXN * HID];
__device__ float g_D[MAXN * HID];
__device__ float g_E[MAXN * HID];
__device__ float g_C[MAXE * HID];      // Ce = e @ W2 + b2
__device__ float g_accsh[MAXN * HID];
__device__ float g_accs[MAXN * HID];
__device__ int   g_off[2048];

// ---------------- misc kernels ----------------

__global__ void embed_kernel(const int* __restrict__ an,
                             const float* __restrict__ emb, int n) {
    int i = blockIdx.x * blockDim.x + threadIdx.x;
    if (i < n * HID) g_h[i] = emb[an[i >> 6] * HID + (i & 63)];
}

__global__ void rbf_kernel(const float* __restrict__ x, const float* __restrict__ W,
                           const float* __restrict__ bias, float* __restrict__ out,
                           int n, int bins, float vmin, float step, float gamma) {
    __shared__ float phi[8 * 80];
    __shared__ float xs[8];
    int tx = threadIdx.x & 31, ez = threadIdx.x >> 5;
    ull bp = *(const ull*)(bias + 2 * tx);
    for (int base = blockIdx.x * 8; base < n; base += gridDim.x * 8) {
        __syncthreads();
        if (threadIdx.x < 8)
            xs[threadIdx.x] = (base + threadIdx.x < n) ? x[base + threadIdx.x] : 0.f;
        __syncthreads();
        for (int idx = threadIdx.x; idx < 8 * bins; idx += 256) {
            int ee = idx / bins, k = idx - ee * bins;
            float dd = xs[ee] - (vmin + k * step);
            phi[idx] = __expf(-gamma * dd * dd);
        }
        __syncthreads();
        int eid = base + ez;
        if (eid < n) {
            ull acc = bp;
            for (int k = 0; k < bins; k++) {
                float p = phi[ez * bins + k];
                fma2(acc, pack2(p, p), __ldg((const ull*)(W + k * HID + 2 * tx)));
            }
            *(ull*)(out + (size_t)eid * HID + 2 * tx) = acc;
        }
    }
}

// ---------------- GEMM kernels (row-pair packed FFMA2) ----------------

// A,B,D,E = h @ {W0,W1,W3,W4} + bias; also zeroes g_accsh/g_accs rows.
// Tile = 128 rows. Warp handles 8 row-pairs (16 rows), output split tx / tx+32.
// Dynamic smem: Ws[4*4096] floats (64KB) + xsi[64*64] ull (32KB) = 96KB.
__global__ void __launch_bounds__(256, 2) gemm4_kernel(
    const float* __restrict__ h, const float* __restrict__ W,
    const float* __restrict__ bias, int n) {
    extern __shared__ __align__(16) float smem[];
    float* Ws = smem;                       // 4 * 4096 floats
    ull* xsi = (ull*)(smem + 4 * 4096);     // 64 pairs * 64 k
    int tx = threadIdx.x & 31, wz = threadIdx.x >> 5;
    const int msel0 = 0, msel1 = 1, msel2 = 3, msel3 = 4;
    for (int i = threadIdx.x; i < 4096; i += 256) {
        Ws[0 * 4096 + i] = W[msel0 * 4096 + i];
        Ws[1 * 4096 + i] = W[msel1 * 4096 + i];
        Ws[2 * 4096 + i] = W[msel2 * 4096 + i];
        Ws[3 * 4096 + i] = W[msel3 * 4096 + i];
    }
    float bb[4][2];
    bb[0][0] = bias[msel0 * 64 + tx]; bb[0][1] = bias[msel0 * 64 + tx + 32];
    bb[1][0] = bias[msel1 * 64 + tx]; bb[1][1] = bias[msel1 * 64 + tx + 32];
    bb[2][0] = bias[msel2 * 64 + tx]; bb[2][1] = bias[msel2 * 64 + tx + 32];
    bb[3][0] = bias[msel3 * 64 + tx]; bb[3][1] = bias[msel3 * 64 + tx + 32];

    for (int base = blockIdx.x * 128; base < n; base += gridDim.x * 128) {
        __syncthreads();
        // stage interleaved row-pairs
        for (int t = threadIdx.x; t < 1024; t += 256) {
            int p = t >> 4, k4 = t & 15;
            int r0 = base + 2 * p, r1 = r0 + 1;
            float4 a = make_float4(0.f, 0.f, 0.f, 0.f), b = a;
            if (r0 < n) a = *(const float4*)(h + (size_t)r0 * 64 + k4 * 4);
            if (r1 < n) b = *(const float4*)(h + (size_t)r1 * 64 + k4 * 4);
            ull* dst = xsi + p * 64 + k4 * 4;
            dst[0] = pack2(a.x, b.x); dst[1] = pack2(a.y, b.y);
            dst[2] = pack2(a.z, b.z); dst[3] = pack2(a.w, b.w);
        }
        // zero segment accumulators for this tile
        {
            float4 z = make_float4(0.f, 0.f, 0.f, 0.f);
            for (int t = threadIdx.x; t < 128 * 16; t += 256) {
                int r = base + (t >> 4);
                if (r < n) {
                    size_t o = (size_t)r * 64 + (t & 15) * 4;
                    *(float4*)(g_accsh + o) = z;
                    *(float4*)(g_accs + o)  = z;
                }
            }
        }
        __syncthreads();
        int p0 = wz * 8;
#pragma unroll
        for (int pass = 0; pass < 2; pass++) {
            const float* Wa = Ws + (2 * pass) * 4096;
            const float* Wb = Ws + (2 * pass + 1) * 4096;
            ull acc[2][2][8];
#pragma unroll
            for (int p = 0; p < 8; p++) {
                acc[0][0][p] = pack2(bb[2 * pass][0], bb[2 * pass][0]);
                acc[0][1][p] = pack2(bb[2 * pass][1], bb[2 * pass][1]);
                acc[1][0][p] = pack2(bb[2 * pass + 1][0], bb[2 * pass + 1][0]);
                acc[1][1][p] = pack2(bb[2 * pass + 1][1], bb[2 * pass + 1][1]);
            }
#pragma unroll 8
            for (int k = 0; k < 64; k++) {
                float wa0 = Wa[k * 64 + tx], wa1 = Wa[k * 64 + tx + 32];
                float wb0 = Wb[k * 64 + tx], wb1 = Wb[k * 64 + tx + 32];
                ull wda0 = pack2(wa0, wa0), wda1 = pack2(wa1, wa1);
                ull wdb0 = pack2(wb0, wb0), wdb1 = pack2(wb1, wb1);
#pragma unroll
                for (int p = 0; p < 8; p++) {
                    ull xb = xsi[(p0 + p) * 64 + k];
                    fma2(acc[0][0][p], xb, wda0);
                    fma2(acc[0][1][p], xb, wda1);
                    fma2(acc[1][0][p], xb, wdb0);
                    fma2(acc[1][1][p], xb, wdb1);
                }
            }
            float* buf0 = (pass == 0) ? g_A : g_D;
            float* buf1 = (pass == 0) ? g_B : g_E;
#pragma unroll
            for (int p = 0; p < 8; p++) {
                int r0 = base + 2 * (p0 + p), r1 = r0 + 1;
#pragma unroll
                for (int jh = 0; jh < 2; jh++) {
                    float l0, h0, l1, h1;
                    unpack2(acc[0][jh][p], l0, h0);
                    unpack2(acc[1][jh][p], l1, h1);
                    int col = tx + 32 * jh;
                    if (r0 < n) {
                        buf0[(size_t)r0 * 64 + col] = l0;
                        buf1[(size_t)r0 * 64 + col] = l1;
                    }
                    if (r1 < n) {
                        buf0[(size_t)r1 * 64 + col] = h0;
                        buf1[(size_t)r1 * 64 + col] = h1;
                    }
                }
            }
        }
    }
}

// Ce = x @ W2 + b2. Tile = 256 rows; warp handles 16 row-pairs.
// Dynamic smem: Ws[4096] floats (16KB) + xsi[128*64] ull (64KB) = 80KB.
__global__ void __launch_bounds__(256, 2) gemm1_kernel(
    const float* __restrict__ x, const float* __restrict__ W2,
    const float* __restrict__ b2, float* __restrict__ out, int n) {
    extern __shared__ __align__(16) float smem[];
    float* Ws = smem;                   // 4096 floats
    ull* xsi = (ull*)(smem + 4096);     // 128 pairs * 64 k
    int tx = threadIdx.x & 31, wz = threadIdx.x >> 5;
    for (int i = threadIdx.x; i < 4096; i += 256) Ws[i] = W2[i];
    float b0 = b2[tx], b1 = b2[tx + 32];

    for (int base = blockIdx.x * 256; base < n; base += gridDim.x * 256) {
        __syncthreads();
        for (int t = threadIdx.x; t < 2048; t += 256) {
            int p = t >> 4, k4 = t & 15;
            int r0 = base + 2 * p, r1 = r0 + 1;
            float4 a = make_float4(0.f, 0.f, 0.f, 0.f), b = a;
            if (r0 < n) a = *(const float4*)(x + (size_t)r0 * 64 + k4 * 4);
            if (r1 < n) b = *(const float4*)(x + (size_t)r1 * 64 + k4 * 4);
            ull* dst = xsi + p * 64 + k4 * 4;
            dst[0] = pack2(a.x, b.x); dst[1] = pack2(a.y, b.y);
            dst[2] = pack2(a.z, b.z); dst[3] = pack2(a.w, b.w);
        }
        __syncthreads();
        int p0 = wz * 16;
        ull acc[2][16];
#pragma unroll
        for (int p = 0; p < 16; p++) {
            acc[0][p] = pack2(b0, b0);
            acc[1][p] = pack2(b1, b1);
        }
#pragma unroll 8
        for (int k = 0; k < 64; k++) {
            float w0 = Ws[k * 64 + tx], w1 = Ws[k * 64 + tx + 32];
            ull wd0 = pack2(w0, w0), wd1 = pack2(w1, w1);
#pragma unroll
            for (int p = 0; p < 16; p++) {
                ull xb = xsi[(p0 + p) * 64 + k];
                fma2(acc[0][p], xb, wd0);
                fma2(acc[1][p], xb, wd1);
            }
        }
#pragma unroll
        for (int p = 0; p < 16; p++) {
            int r0 = base + 2 * (p0 + p), r1 = r0 + 1;
#pragma unroll
            for (int jh = 0; jh < 2; jh++) {
                float lo, hi;
                unpack2(acc[jh][p], lo, hi);
                int col = tx + 32 * jh;
                if (r0 < n) out[(size_t)r0 * 64 + col] = lo;
                if (r1 < n) out[(size_t)r1 * 64 + col] = hi;
            }
        }
    }
}

// ---------------- gather / scatter kernels ----------------

// Per edge: e_new = D[src]+E[dst]+Ce; sigma; atomic segment sums; optional e += silu.
__global__ void edge2_kernel(const int* __restrict__ src, const int* __restrict__ dst,
                             float* __restrict__ e, int E, int write_e) {
    int tx = threadIdx.x & 31;
    int gw = (blockIdx.x * blockDim.x + threadIdx.x) >> 5;
    int nw = (gridDim.x * blockDim.x) >> 5;
    for (int eid = gw; eid < E; eid += nw) {
        int s = __ldg(src + eid);
        int d = __ldg(dst + eid);
        size_t eo = (size_t)eid * 64 + 2 * tx;
        size_t so = (size_t)s * 64 + 2 * tx;
        size_t dofs = (size_t)d * 64 + 2 * tx;
        float2 ce = __ldg((const float2*)(g_C + eo));
        float2 dh = __ldg((const float2*)(g_D + so));
        float2 eh = __ldg((const float2*)(g_E + dofs));
        float2 bh = __ldg((const float2*)(g_B + so));
        float en0 = dh.x + eh.x + ce.x;
        float en1 = dh.y + eh.y + ce.y;
        float sg0 = 1.f / (1.f + __expf(-en0));
        float sg1 = 1.f / (1.f + __expf(-en1));
        atomicAdd(g_accsh + dofs,     bh.x * sg0);
        atomicAdd(g_accsh + dofs + 1, bh.y * sg1);
        atomicAdd(g_accs + dofs,      sg0);
        atomicAdd(g_accs + dofs + 1,  sg1);
        if (write_e) {
            float2 ev = *(const float2*)(e + eo);
            ev.x += en0 * sg0;
            ev.y += en1 * sg1;
            *(float2*)(e + eo) = ev;
        }
    }
}

__global__ void node_kernel(float* __restrict__ h, int n) {
    int i = blockIdx.x * blockDim.x + threadIdx.x;
    if (i < n * HID) {
        float hn = g_A[i] + g_accsh[i] / (g_accs[i] + 1e-6f);
        h[i] += hn / (1.f + __expf(-hn));
    }
}

__global__ void offsets_kernel(const int* __restrict__ len, int Bc) {
    if (threadIdx.x == 0 && blockIdx.x == 0) {
        int o = 0;
        for (int b = 0; b < Bc && b < 2048; b++) { g_off[b] = o; o += len[b]; }
    }
}

__global__ void out_kernel(const float* __restrict__ h, const float* __restrict__ fcW,
                           const float* __restrict__ fcb, const int* __restrict__ len,
                           float* __restrict__ out, int n_nodes, int Bc, int L, int TH,
                           int with_mask) {
    __shared__ float hsh[HID];
    int row = blockIdx.x;
    int b = row / L, j = row - b * L;
    int lenb = len[b];
    int m = (j < lenb) ? 1 : 0;
    if (with_mask && threadIdx.x == 0)
        out[(size_t)Bc * L * TH + row] = (float)m;
    size_t ro = (size_t)row * TH;
    if (!m) {
        for (int t = threadIdx.x; t < TH; t += blockDim.x) out[ro + t] = 0.f;
        return;
    }
    int node = g_off[b] + j;
    if (node >= n_nodes) node = n_nodes - 1;
    if (node < 0) node = 0;
    if (threadIdx.x < HID) hsh[threadIdx.x] = h[(size_t)node * HID + threadIdx.x];
    __syncthreads();
    for (int t = threadIdx.x; t < TH; t += blockDim.x) {
        float acc = fcb[t];
#pragma unroll
        for (int k = 0; k < HID; k++)
            acc = fmaf(hsh[k], __ldg(fcW + k * TH + t), acc);
        out[ro + t] = acc;
    }
}

// ---------------- host ----------------

extern "C" void kernel_launch(void* const* d_in, const int* in_sizes, int n_in,
                              void* d_out, int out_size) {
    const int*   an   = (const int*)d_in[0];
    const int*   src  = (const int*)d_in[1];
    const int*   dst  = (const int*)d_in[2];
    const int*   lsrc = (const int*)d_in[3];
    const int*   ldst = (const int*)d_in[4];
    const float* dist = (const float*)d_in[5];
    const float* ang  = (const float*)d_in[6];
    const int*   clen = (const int*)d_in[7];
    const float* emb  = (const float*)d_in[8];
    const float* eW   = (const float*)d_in[9];
    const float* eb   = (const float*)d_in[10];
    const float* aW   = (const float*)d_in[11];
    const float* ab   = (const float*)d_in[12];
    const float* Wg   = (const float*)d_in[13];
    const float* bg   = (const float*)d_in[14];
    const float* fcW  = (const float*)d_in[15];
    const float* fcb  = (const float*)d_in[16];

    int n_nodes = in_sizes[0];
    int n_edges = in_sizes[1];
    int n_lg    = in_sizes[3];
    int Bc      = in_sizes[7];
    int rbf_d   = in_sizes[9] / HID;
    int rbf_t   = in_sizes[11] / HID;
    int TH      = in_sizes[15] / HID;

    float *p_h, *p_e, *p_l, *p_C;
    cudaGetSymbolAddress((void**)&p_h, g_h);
    cudaGetSymbolAddress((void**)&p_e, g_e);
    cudaGetSymbolAddress((void**)&p_l, g_l);
    cudaGetSymbolAddress((void**)&p_C, g_C);

    static int attr_done = 0;
    (void)attr_done;
    cudaFuncSetAttribute(gemm4_kernel, cudaFuncAttributeMaxDynamicSharedMemorySize, 98304);
    cudaFuncSetAttribute(gemm1_kernel, cudaFuncAttributeMaxDynamicSharedMemorySize, 81920);

    long long per = (long long)out_size / Bc;
    int L, with_mask;
    if (per % (TH + 1) == 0) { L = (int)(per / (TH + 1)); with_mask = 1; }
    else                     { L = (int)(per / TH);       with_mask = 0; }

    const int GS = 148 * 8;

    embed_kernel<<<(n_nodes * HID + 255) / 256, 256>>>(an, emb, n_nodes);
    rbf_kernel<<<GS, 256>>>(dist, eW, eb, p_e, n_edges, rbf_d,
                            0.f, 8.f / (rbf_d - 1), (rbf_d - 1) / 8.f);
    rbf_kernel<<<GS, 256>>>(ang, aW, ab, p_l, n_lg, rbf_t,
                            -1.f, 2.f / (rbf_t - 1), (rbf_t - 1) / 2.f);

    struct GcnArgs { const int* s; const int* d; int n; int E; float* hb; float* ebuf; int layer; int we; };
    GcnArgs seq[6] = {
        { src,  dst,  n_nodes, n_edges, p_h, p_e, 0, 1 },
        { lsrc, ldst, n_edges, n_lg,    p_e, p_l, 1, 1 },
        { src,  dst,  n_nodes, n_edges, p_h, p_e, 2, 1 },
        { lsrc, ldst, n_edges, n_lg,    p_e, p_l, 3, 1 },
        { src,  dst,  n_nodes, n_edges, p_h, p_e, 4, 0 },
        { src,  dst,  n_nodes, n_edges, p_h, p_e, 5, 0 },
    };
    for (int i = 0; i < 6; i++) {
        const GcnArgs& a = seq[i];
        const float* Wl = Wg + (size_t)a.layer * 5 * 4096;
        const float* bl = bg + (size_t)a.layer * 5 * 64;
        int tiles4 = (a.n + 127) / 128;
        int tiles1 = (a.E + 255) / 256;
        gemm4_kernel<<<min(GS, tiles4), 256, 98304>>>(a.hb, Wl, bl, a.n);
        gemm1_kernel<<<min(GS, tiles1), 256, 81920>>>(a.ebuf, Wl + 2 * 4096, bl + 2 * 64, p_C, a.E);
        edge2_kernel<<<GS, 256>>>(a.s, a.d, a.ebuf, a.E, a.we);
        node_kernel<<<(a.n * HID + 255) / 256, 256>>>(a.hb, a.n);
    }

    offsets_kernel<<<1, 32>>>(clen, Bc);
    out_kernel<<<Bc * L, 256>>>(p_h, fcW, fcb, clen, (float*)d_out,
                                n_nodes, Bc, L, TH, with_mask);
}